// round 14
// baseline (speedup 1.0000x reference)
#include <cuda_runtime.h>
#include <cstdint>

// Problem constants (fixed by reference setup_inputs)
#define Bn 16
#define Cn 128
#define TA 2048
#define TB 1024
#define Rn TA   // reference timeline = modality A
#define GC 8    // channels per block

// Output layout (float32, flattened in return order)
#define OFF_ALIGNED 0
#define OFF_MASK    8388608
#define OFF_IDX     8454144
#define OFF_RATIO   8519680

// -----------------------------------------------------------------------------
// Fully fused kernel: compaction + binary search + mask/idx/ratio + gather.
// Grid: 512 blocks of 512 threads; blockIdx.x -> (mb = m*16+b, ctile of 8 ch).
// Each block:
//   1. compacts the valid sources of its (m,b) row into smem (order-preserving:
//      compacted order == original index order, timestamps stay sorted)
//   2. binary-searches all 2048 reference timestamps (4 per thread) -> s_idx
//      (exact JAX tie-breaks: equal distance -> left; duplicates -> first)
//   3. ctile==0 blocks write aligned_mask, src_idx, valid_ratio
//   4. gathers its 8 channels: thread t serves float4 r-granule t for all 8
//      channels with one int4 index vector (R10 form, best measured).
// -----------------------------------------------------------------------------
__global__ __launch_bounds__(512)
void fused_kernel(const float* __restrict__ ta, const float* __restrict__ ma,  // A t,m [B,TA]
                  const float* __restrict__ tb, const float* __restrict__ mb_, // B t,m [B,TB]
                  const float* __restrict__ va, const float* __restrict__ vb,  // values [B,C,S]
                  float* __restrict__ aligned,   // [2,B,C,R]
                  float* __restrict__ mask_out,  // [2,B,R]
                  float* __restrict__ idx_out,   // [2,B,R]
                  float* __restrict__ ratio)     // [2,B]
{
    __shared__ float s_t[2048];
    __shared__ int   s_i[2048];
    __shared__ int   s_idx[2048];
    __shared__ int   wtot[16], woff[16];
    __shared__ int   s_cnt;

    const int t     = threadIdx.x;
    const int ctile = blockIdx.x & 15;
    const int mb    = blockIdx.x >> 4;    // 0..31
    const int m     = mb >> 4;
    const int b     = mb & 15;
    const int S     = m ? TB : TA;
    const int lane  = t & 31, wid = t >> 5;

    const float* src_t = (m ? tb : ta) + (size_t)b * S;
    const float* src_m = (m ? mb_ : ma) + (size_t)b * S;

    // ---- 1. order-preserving compaction into smem ----
    const int per  = S >> 9;              // 4 (A) or 2 (B)
    const int base = t * per;

    float v_t[4], v_m[4];
    #pragma unroll
    for (int i = 0; i < 4; i++) {
        if (i < per) { v_t[i] = src_t[base + i]; v_m[i] = src_m[base + i]; }
    }
    int cnt = 0;
    #pragma unroll
    for (int i = 0; i < 4; i++)
        if (i < per) cnt += (v_m[i] > 0.0f) ? 1 : 0;

    // block scan over 512 threads: warp shuffle scan + 16-wide warp-total scan
    int inc = cnt;
    #pragma unroll
    for (int off = 1; off < 32; off <<= 1) {
        int v = __shfl_up_sync(0xffffffffu, inc, off);
        if (lane >= off) inc += v;
    }
    if (lane == 31) wtot[wid] = inc;
    if (t == 0) s_cnt = 0;
    __syncthreads();
    if (t < 16) {
        int v = wtot[t];
        int s = v;
        #pragma unroll
        for (int off = 1; off < 16; off <<= 1) {
            int u = __shfl_up_sync(0x0000ffffu, s, off);
            if (t >= off) s += u;
        }
        woff[t] = s - v;                  // exclusive warp offset
    }
    __syncthreads();

    int pos = woff[wid] + inc - cnt;      // exclusive prefix for this thread
    #pragma unroll
    for (int i = 0; i < 4; i++) {
        if (i < per && v_m[i] > 0.0f) {
            s_t[pos] = v_t[i];
            s_i[pos] = base + i;
            pos++;
        }
    }
    const int nv = woff[15] + wtot[15];   // total valid count
    __syncthreads();

    // ---- 2. binary search: 2048 refs, 4 per thread ----
    const float* ref_t = ta + (size_t)b * Rn;
    const float* ref_m = ma + (size_t)b * Rn;
    const bool  emit   = (ctile == 0);

    int c2 = 0;                           // count of valid A-mask entries (for ratio)
    #pragma unroll
    for (int j = 0; j < 4; j++) {
        const int r = t + 512 * j;
        const float rt = ref_t[r];
        const float rm = ref_m[r];
        c2 += (rm > 0.0f) ? 1 : 0;
        const bool ok = (rm > 0.0f) && (nv > 0);

        int idx = -1;
        if (ok) {
            int lo = 0, hi = nv;          // lower_bound: first s_t[pos] >= rt
            while (lo < hi) {
                int mid = (lo + hi) >> 1;
                if (s_t[mid] < rt) lo = mid + 1; else hi = mid;
            }
            int p;
            if (lo == 0) {
                p = 0;                                      // only right candidate
            } else if (lo == nv || (rt - s_t[lo - 1]) <= (s_t[lo] - rt)) {
                float tl = s_t[lo - 1];
                p = lo - 1;
                while (p > 0 && s_t[p - 1] == tl) p--;      // first duplicate
            } else {
                p = lo;                                     // lo is first occurrence
            }
            idx = s_i[p];
        }
        s_idx[r] = idx;
        if (emit) {
            mask_out[(size_t)mb * Rn + r] = ok ? 1.0f : 0.0f;
            idx_out [(size_t)mb * Rn + r] = ok ? (float)idx : -1.0f;
        }
    }
    // block-wide count of valid A refs (needed for m=1 ratio; cheap everywhere)
    #pragma unroll
    for (int off = 16; off > 0; off >>= 1)
        c2 += __shfl_down_sync(0xffffffffu, c2, off);
    if (lane == 0) atomicAdd(&s_cnt, c2);
    __syncthreads();

    // ---- 3. valid_ratio ----
    if (emit && t == 0) {
        // ratio[m,b] = (any src valid ? nvA : 0) / 2048; nvA = #valid masks_a[b]
        int nvA = (m == 0) ? nv : s_cnt;
        ratio[mb] = (nv > 0 ? (float)nvA : 0.0f) * (1.0f / (float)Rn);
    }

    // ---- 4. gather: 8 channels, float4 r-granule t per thread ----
    const float* vals  = m ? vb : va;
    const float* vbase = vals + ((size_t)b * Cn + ctile * GC) * S;
    float*       obase = aligned + ((size_t)mb * Cn + ctile * GC) * Rn + t * 4;

    const int4 ix = *(const int4*)(s_idx + t * 4);
    const bool vx = ix.x >= 0, vy = ix.y >= 0, vz = ix.z >= 0, vw = ix.w >= 0;

    #pragma unroll
    for (int c = 0; c < GC; c++) {
        const float* vrow = vbase + (size_t)c * S;
        float4 o;
        o.x = vx ? __ldg(vrow + ix.x) : 0.0f;
        o.y = vy ? __ldg(vrow + ix.y) : 0.0f;
        o.z = vz ? __ldg(vrow + ix.z) : 0.0f;
        o.w = vw ? __ldg(vrow + ix.w) : 0.0f;
        *(float4*)(obase + (size_t)c * Rn) = o;
    }
}

extern "C" void kernel_launch(void* const* d_in, const int* in_sizes, int n_in,
                              void* d_out, int out_size)
{
    const float* values_a     = (const float*)d_in[0];
    const float* timestamps_a = (const float*)d_in[1];
    const float* masks_a      = (const float*)d_in[2];
    const float* values_b     = (const float*)d_in[3];
    const float* timestamps_b = (const float*)d_in[4];
    const float* masks_b      = (const float*)d_in[5];
    float* out = (float*)d_out;

    float* aligned = out + OFF_ALIGNED;
    float* maskout = out + OFF_MASK;   // [2,B,R]
    float* idxout  = out + OFF_IDX;    // [2,B,R]
    float* ratio   = out + OFF_RATIO;  // [2,B]

    // One launch: align + outputs + gather.
    fused_kernel<<<512, 512>>>(timestamps_a, masks_a, timestamps_b, masks_b,
                               values_a, values_b,
                               aligned, maskout, idxout, ratio);

    (void)in_sizes; (void)n_in; (void)out_size;
}

// round 15
// speedup vs baseline: 1.2593x; 1.2593x over previous
#include <cuda_runtime.h>
#include <cstdint>

// Problem constants (fixed by reference setup_inputs)
#define Bn 16
#define Cn 128
#define TA 2048
#define TB 1024
#define Rn TA   // reference timeline = modality A
#define GC 8    // channels per gather thread

// Output layout (float32, flattened in return order)
#define OFF_ALIGNED 0
#define OFF_MASK    8388608
#define OFF_IDX     8454144
#define OFF_RATIO   8519680

// Integer copy of the nearest-index table (avoids float->int cvt in gather)
__device__ int d_idxi[32 * 2048];

__device__ __forceinline__ void l2_prefetch(const void* p) {
    asm volatile("prefetch.global.L2 [%0];" :: "l"(p));
}

// -----------------------------------------------------------------------------
// Kernel 1 (R10 proven form, ~2.9us): compaction + binary search + ratio.
// Executes griddepcontrol.launch_dependents at entry so the PDL-launched
// gather can start its L2 prefetch phase concurrently.
// Grid: 256 blocks of 256 threads. blockIdx.x -> (mb = m*16+b, chunk of 256 refs).
// -----------------------------------------------------------------------------
__global__ __launch_bounds__(256)
void align_kernel(const float* __restrict__ ta, const float* __restrict__ ma,  // A t,m [B,TA]
                  const float* __restrict__ tb, const float* __restrict__ mb_, // B t,m [B,TB]
                  float* __restrict__ mask_out,  // [2,B,R]
                  float* __restrict__ idx_out,   // [2,B,R]
                  float* __restrict__ ratio)     // [2,B]
{
    // Allow dependent (gather) grid to launch now; its griddepcontrol.wait
    // still blocks until THIS grid fully completes (correctness-safe).
    asm volatile("griddepcontrol.launch_dependents;");

    __shared__ float s_t[2048];
    __shared__ int   s_i[2048];
    __shared__ int   wtot[8], woff[8];
    __shared__ int   s_nvA;

    const int t     = threadIdx.x;
    const int chunk = blockIdx.x & 7;
    const int mb    = blockIdx.x >> 3;    // 0..31
    const int m     = mb >> 4;
    const int b     = mb & 15;
    const int S     = m ? TB : TA;

    const float* src_t = (m ? tb : ta) + (size_t)b * S;
    const float* src_m = (m ? mb_ : ma) + (size_t)b * S;

    // ---- order-preserving compaction into smem ----
    const int per  = S >> 8;              // 8 (A) or 4 (B)
    const int base = t * per;
    const int lane = t & 31, wid = t >> 5;

    float v_t[8];
    float v_m[8];
    #pragma unroll
    for (int i = 0; i < 8; i++) {
        if (i < per) {
            v_t[i] = src_t[base + i];
            v_m[i] = src_m[base + i];
        }
    }
    int cnt = 0;
    #pragma unroll
    for (int i = 0; i < 8; i++)
        if (i < per) cnt += (v_m[i] > 0.0f) ? 1 : 0;

    // block scan: warp shuffle scan + warp-total scan
    int inc = cnt;
    #pragma unroll
    for (int off = 1; off < 32; off <<= 1) {
        int v = __shfl_up_sync(0xffffffffu, inc, off);
        if (lane >= off) inc += v;
    }
    if (lane == 31) wtot[wid] = inc;
    __syncthreads();
    if (t < 8) {
        int v = wtot[t];
        int s = v;
        #pragma unroll
        for (int off = 1; off < 8; off <<= 1) {
            int u = __shfl_up_sync(0x000000ffu, s, off);
            if (t >= off) s += u;
        }
        woff[t] = s - v;                  // exclusive warp offset
    }
    __syncthreads();

    int pos = woff[wid] + inc - cnt;      // exclusive prefix for this thread
    #pragma unroll
    for (int i = 0; i < 8; i++) {
        if (i < per && v_m[i] > 0.0f) {
            s_t[pos] = v_t[i];
            s_i[pos] = base + i;
            pos++;
        }
    }
    const int nv = woff[7] + wtot[7];     // total valid count
    __syncthreads();

    // ---- binary search: 256 refs per block, one per thread ----
    const int r = chunk * 256 + t;
    const float rt = ta[(size_t)b * Rn + r];
    const bool ok = (ma[(size_t)b * Rn + r] > 0.0f) && (nv > 0);

    int idx = -1;
    if (ok) {
        int lo = 0, hi = nv;              // lower_bound: first s_t[pos] >= rt
        while (lo < hi) {
            int mid = (lo + hi) >> 1;
            if (s_t[mid] < rt) lo = mid + 1; else hi = mid;
        }
        int p;
        if (lo == 0) {
            p = 0;                                      // only right candidate
        } else if (lo == nv || (rt - s_t[lo - 1]) <= (s_t[lo] - rt)) {
            float tl = s_t[lo - 1];
            p = lo - 1;
            while (p > 0 && s_t[p - 1] == tl) p--;      // first duplicate
        } else {
            p = lo;                                     // lo is first occurrence
        }
        idx = s_i[p];
    }
    mask_out[(size_t)mb * Rn + r] = ok ? 1.0f : 0.0f;
    idx_out [(size_t)mb * Rn + r] = ok ? (float)idx : -1.0f;
    d_idxi  [(size_t)mb * Rn + r] = ok ? idx : -1;

    // ---- valid_ratio (chunk-0 blocks only) ----
    if (chunk == 0) {
        // ratio[m,b] = (nv>0 ? nvA : 0) / 2048, nvA = #valid in masks_a[b].
        if (m == 0) {
            if (t == 0)
                ratio[mb] = (nv > 0 ? (float)nv : 0.0f) * (1.0f / (float)Rn);
        } else {
            if (t == 0) s_nvA = 0;
            __syncthreads();
            const float* am = ma + (size_t)b * TA;
            int c2 = 0;
            #pragma unroll
            for (int i = 0; i < 8; i++)
                c2 += (am[t * 8 + i] > 0.0f) ? 1 : 0;
            #pragma unroll
            for (int off = 16; off > 0; off >>= 1)
                c2 += __shfl_down_sync(0xffffffffu, c2, off);
            if (lane == 0) atomicAdd(&s_nvA, c2);
            __syncthreads();
            if (t == 0)
                ratio[mb] = (nv > 0 ? (float)s_nvA : 0.0f) * (1.0f / (float)Rn);
        }
    }
}

// -----------------------------------------------------------------------------
// Kernel 2: gather (R10 best-measured form) with a PDL pre-dependency phase:
// before griddepcontrol.wait, each block prefetches into L2 the exact value
// window it will read (idx range is bounded by the sorted timelines:
// m=0 -> r-window, m=1 -> r/2-window; prefetch is a hint, misses are fine).
// grid: mb(32) x ctile(16) x rtile(2) = 1024 blocks of 256 threads.
// -----------------------------------------------------------------------------
__global__ __launch_bounds__(256)
void gather_kernel(const float* __restrict__ vals_a,  // [B,C,TA]
                   const float* __restrict__ vals_b,  // [B,C,TB]
                   float* __restrict__ out)           // [2,B,C,R]
{
    const int bid   = blockIdx.x;
    const int rtile = bid & 1;
    const int ctile = (bid >> 1) & 15;
    const int mb    = bid >> 5;           // 0..31
    const int m     = mb >> 4;
    const int b     = mb & 15;
    const int S     = m ? TB : TA;
    const float* vals = m ? vals_b : vals_a;

    const float* vbase = vals + ((size_t)b * Cn + ctile * GC) * S;

    // ---- pre-dependency: L2 prefetch of this block's value window ----
    {
        const int halfS      = S >> 1;               // floats per half-row
        const int linesPerCh = halfS >> 5;           // 128B lines (32 fl/line)
        const char* pf = (const char*)(vbase + rtile * halfS);
        for (int i = threadIdx.x; i < GC * linesPerCh; i += 256) {
            int ch = i / linesPerCh, ln = i - ch * linesPerCh;
            l2_prefetch(pf + (size_t)ch * S * 4 + (size_t)ln * 128);
        }
    }

    // ---- wait for align_kernel completion (memory visible after this) ----
    asm volatile("griddepcontrol.wait;");

    const int r4 = rtile * 256 + threadIdx.x;   // 0..511 (float4 granules of r)

    const int4 ix = __ldg((const int4*)(d_idxi + (size_t)mb * Rn) + r4);
    const bool vx = ix.x >= 0, vy = ix.y >= 0, vz = ix.z >= 0, vw = ix.w >= 0;

    float* obase = out + ((size_t)mb * Cn + ctile * GC) * Rn + r4 * 4;

    #pragma unroll
    for (int c = 0; c < GC; c++) {
        const float* vrow = vbase + (size_t)c * S;
        float4 o;
        o.x = vx ? __ldg(vrow + ix.x) : 0.0f;
        o.y = vy ? __ldg(vrow + ix.y) : 0.0f;
        o.z = vz ? __ldg(vrow + ix.z) : 0.0f;
        o.w = vw ? __ldg(vrow + ix.w) : 0.0f;
        *(float4*)(obase + (size_t)c * Rn) = o;
    }
}

extern "C" void kernel_launch(void* const* d_in, const int* in_sizes, int n_in,
                              void* d_out, int out_size)
{
    const float* values_a     = (const float*)d_in[0];
    const float* timestamps_a = (const float*)d_in[1];
    const float* masks_a      = (const float*)d_in[2];
    const float* values_b     = (const float*)d_in[3];
    const float* timestamps_b = (const float*)d_in[4];
    const float* masks_b      = (const float*)d_in[5];
    float* out = (float*)d_out;

    float* aligned = out + OFF_ALIGNED;
    float* maskout = out + OFF_MASK;   // [2,B,R]
    float* idxout  = out + OFF_IDX;    // [2,B,R]
    float* ratio   = out + OFF_RATIO;  // [2,B]

    // Phase 1: align (fires launch_dependents at entry)
    align_kernel<<<256, 256>>>(timestamps_a, masks_a, timestamps_b, masks_b,
                               maskout, idxout, ratio);

    // Phase 2: gather, PDL-launched so its prefetch phase overlaps align.
    {
        cudaLaunchConfig_t cfg = {};
        cfg.gridDim  = dim3(1024, 1, 1);
        cfg.blockDim = dim3(256, 1, 1);
        cfg.dynamicSmemBytes = 0;
        cfg.stream = 0;
        cudaLaunchAttribute attr[1];
        attr[0].id = cudaLaunchAttributeProgrammaticStreamSerialization;
        attr[0].val.programmaticStreamSerializationAllowed = 1;
        cfg.attrs = attr;
        cfg.numAttrs = 1;
        cudaLaunchKernelEx(&cfg, gather_kernel, values_a, values_b, aligned);
    }

    (void)in_sizes; (void)n_in; (void)out_size;
}

// round 16
// speedup vs baseline: 1.4088x; 1.1187x over previous
#include <cuda_runtime.h>
#include <cstdint>

// Problem constants (fixed by reference setup_inputs)
#define Bn 16
#define Cn 128
#define TA 2048
#define TB 1024
#define Rn TA   // reference timeline = modality A

// Output layout (float32, flattened in return order)
#define OFF_ALIGNED 0
#define OFF_MASK    8388608
#define OFF_IDX     8454144
#define OFF_RATIO   8519680

// -----------------------------------------------------------------------------
// Fused kernel, non-redundant search.
// Grid: 512 blocks of 512 threads; blockIdx.x -> (mb = m*16+b, rchunk 0..15).
// Each block owns the 128-reference stripe r in [rchunk*128, rchunk*128+128):
//   1. compacts the valid sources of its (m,b) row into smem (redundant per
//      rchunk, but L2-resident and cheap; order-preserving so timestamps stay
//      sorted and compacted order == original index order)
//   2. binary-searches ONLY its 128 refs (threads 0..127) -> s_idx, and emits
//      aligned_mask / src_idx for them (exact JAX tie-breaks: equal distance
//      -> left neighbor; duplicate timestamps -> first occurrence)
//   3. rchunk==0 blocks emit valid_ratio
//   4. gathers its stripe for all 128 channels: warp w -> channels w*8..w*8+7,
//      lane -> float4 granule (R10-proven inner loop, idx from smem).
// -----------------------------------------------------------------------------
__global__ __launch_bounds__(512)
void fused_kernel(const float* __restrict__ ta, const float* __restrict__ ma,  // A t,m [B,TA]
                  const float* __restrict__ tb, const float* __restrict__ mb_, // B t,m [B,TB]
                  const float* __restrict__ va, const float* __restrict__ vb,  // values [B,C,S]
                  float* __restrict__ aligned,   // [2,B,C,R]
                  float* __restrict__ mask_out,  // [2,B,R]
                  float* __restrict__ idx_out,   // [2,B,R]
                  float* __restrict__ ratio)     // [2,B]
{
    __shared__ float s_t[2048];
    __shared__ int   s_i[2048];
    __shared__ int   s_idx[128];
    __shared__ int   wtot[16], woff[16];
    __shared__ int   s_nvA;

    const int t      = threadIdx.x;
    const int rchunk = blockIdx.x & 15;
    const int mb     = blockIdx.x >> 4;   // 0..31
    const int m      = mb >> 4;
    const int b      = mb & 15;
    const int S      = m ? TB : TA;
    const int lane   = t & 31, wid = t >> 5;

    const float* src_t = (m ? tb : ta) + (size_t)b * S;
    const float* src_m = (m ? mb_ : ma) + (size_t)b * S;

    if (t == 0) s_nvA = 0;

    // ---- 1. order-preserving compaction into smem (512 threads) ----
    const int per  = S >> 9;              // 4 (A) or 2 (B)
    const int base = t * per;

    float v_t[4], v_m[4];
    #pragma unroll
    for (int i = 0; i < 4; i++) {
        if (i < per) { v_t[i] = src_t[base + i]; v_m[i] = src_m[base + i]; }
    }
    int cnt = 0;
    #pragma unroll
    for (int i = 0; i < 4; i++)
        if (i < per) cnt += (v_m[i] > 0.0f) ? 1 : 0;

    // block scan: warp shuffle scan + 16-wide warp-total scan
    int inc = cnt;
    #pragma unroll
    for (int off = 1; off < 32; off <<= 1) {
        int v = __shfl_up_sync(0xffffffffu, inc, off);
        if (lane >= off) inc += v;
    }
    if (lane == 31) wtot[wid] = inc;
    __syncthreads();
    if (t < 16) {
        int v = wtot[t];
        int s = v;
        #pragma unroll
        for (int off = 1; off < 16; off <<= 1) {
            int u = __shfl_up_sync(0x0000ffffu, s, off);
            if (t >= off) s += u;
        }
        woff[t] = s - v;                  // exclusive warp offset
    }
    __syncthreads();

    int pos = woff[wid] + inc - cnt;      // exclusive prefix for this thread
    #pragma unroll
    for (int i = 0; i < 4; i++) {
        if (i < per && v_m[i] > 0.0f) {
            s_t[pos] = v_t[i];
            s_i[pos] = base + i;
            pos++;
        }
    }
    const int nv = woff[15] + wtot[15];   // total valid count
    __syncthreads();

    // ---- 2. binary search: this block's 128 refs only (threads 0..127) ----
    if (t < 128) {
        const int r = rchunk * 128 + t;
        const float rt = ta[(size_t)b * Rn + r];
        const bool ok = (ma[(size_t)b * Rn + r] > 0.0f) && (nv > 0);

        int idx = -1;
        if (ok) {
            int lo = 0, hi = nv;          // lower_bound: first s_t[pos] >= rt
            while (lo < hi) {
                int mid = (lo + hi) >> 1;
                if (s_t[mid] < rt) lo = mid + 1; else hi = mid;
            }
            int p;
            if (lo == 0) {
                p = 0;                                      // only right candidate
            } else if (lo == nv || (rt - s_t[lo - 1]) <= (s_t[lo] - rt)) {
                float tl = s_t[lo - 1];
                p = lo - 1;
                while (p > 0 && s_t[p - 1] == tl) p--;      // first duplicate
            } else {
                p = lo;                                     // lo is first occurrence
            }
            idx = s_i[p];
        }
        s_idx[t] = idx;
        mask_out[(size_t)mb * Rn + r] = ok ? 1.0f : 0.0f;
        idx_out [(size_t)mb * Rn + r] = ok ? (float)idx : -1.0f;
    }

    // ---- 3. valid_ratio (rchunk==0 blocks) ----
    if (rchunk == 0) {
        // ratio[m,b] = (nv>0 ? nvA : 0) / 2048, nvA = #valid in masks_a[b].
        if (m == 0) {
            if (t == 0)
                ratio[mb] = (nv > 0 ? (float)nv : 0.0f) * (1.0f / (float)Rn);
        } else {
            const float* am = ma + (size_t)b * TA;
            int c2 = 0;
            #pragma unroll
            for (int i = 0; i < 4; i++)
                c2 += (am[t * 4 + i] > 0.0f) ? 1 : 0;
            #pragma unroll
            for (int off = 16; off > 0; off >>= 1)
                c2 += __shfl_down_sync(0xffffffffu, c2, off);
            if (lane == 0) atomicAdd(&s_nvA, c2);
        }
    }
    __syncthreads();                      // s_idx (and s_nvA) visible
    if (rchunk == 0 && m == 1 && t == 0)
        ratio[mb] = (nv > 0 ? (float)s_nvA : 0.0f) * (1.0f / (float)Rn);

    // ---- 4. gather: warp w -> channels w*8..w*8+7, lane -> float4 granule ----
    const float* vals  = m ? vb : va;
    const int    cb    = wid * 8;         // 16 warps x 8 = 128 channels
    const float* vbase = vals + ((size_t)b * Cn + cb) * S;
    float*       obase = aligned + ((size_t)mb * Cn + cb) * Rn
                                 + rchunk * 128 + lane * 4;

    const int4 ix = *(const int4*)(s_idx + lane * 4);
    const bool vx = ix.x >= 0, vy = ix.y >= 0, vz = ix.z >= 0, vw = ix.w >= 0;

    #pragma unroll
    for (int c = 0; c < 8; c++) {
        const float* vrow = vbase + (size_t)c * S;
        float4 o;
        o.x = vx ? __ldg(vrow + ix.x) : 0.0f;
        o.y = vy ? __ldg(vrow + ix.y) : 0.0f;
        o.z = vz ? __ldg(vrow + ix.z) : 0.0f;
        o.w = vw ? __ldg(vrow + ix.w) : 0.0f;
        *(float4*)(obase + (size_t)c * Rn) = o;
    }
}

extern "C" void kernel_launch(void* const* d_in, const int* in_sizes, int n_in,
                              void* d_out, int out_size)
{
    const float* values_a     = (const float*)d_in[0];
    const float* timestamps_a = (const float*)d_in[1];
    const float* masks_a      = (const float*)d_in[2];
    const float* values_b     = (const float*)d_in[3];
    const float* timestamps_b = (const float*)d_in[4];
    const float* masks_b      = (const float*)d_in[5];
    float* out = (float*)d_out;

    float* aligned = out + OFF_ALIGNED;
    float* maskout = out + OFF_MASK;   // [2,B,R]
    float* idxout  = out + OFF_IDX;    // [2,B,R]
    float* ratio   = out + OFF_RATIO;  // [2,B]

    // Single launch: compaction + non-redundant search + outputs + gather.
    fused_kernel<<<512, 512>>>(timestamps_a, masks_a, timestamps_b, masks_b,
                               values_a, values_b,
                               aligned, maskout, idxout, ratio);

    (void)in_sizes; (void)n_in; (void)out_size;
}

// round 17
// speedup vs baseline: 1.6394x; 1.1637x over previous
#include <cuda_runtime.h>
#include <cstdint>

// Problem constants (fixed by reference setup_inputs)
#define Bn 16
#define Cn 128
#define TA 2048
#define TB 1024
#define Rn TA   // reference timeline = modality A

// Output layout (float32, flattened in return order)
#define OFF_ALIGNED 0
#define OFF_MASK    8388608
#define OFF_IDX     8454144
#define OFF_RATIO   8519680

// -----------------------------------------------------------------------------
// Fused kernel, m-specialized front end.
// Grid: 512 blocks of 512 threads; blockIdx.x -> (mb = m*16+b, rchunk 0..15).
// Each block owns the 128-ref stripe r in [rchunk*128, rchunk*128+128).
//
//   m=0 (A->A): NO compaction, NO search. If masks_a[r] > 0 then source r is
//     valid at distance 0, so nv>0 is implied and idx = r — except duplicate
//     timestamps, resolved exactly by an O(1)-expected walk-back (run start of
//     equal timestamps, then first valid index in the run; exists since r is
//     valid). If masks_a[r] <= 0, ok = false.
//   m=1 (B->A): order-preserving compaction of the B row into smem (1024
//     elems, 2/thread) + binary search of the block's 128 refs, exact JAX
//     tie-breaks (equal distance -> left; duplicate timestamps -> first).
//
//   rchunk==0 blocks emit valid_ratio:
//     ratio[0,b] = nvA/2048   (exact also when nvA==0)
//     ratio[1,b] = (nv>0 ? nvA : 0)/2048
//
//   Gather (all blocks): warp w -> channels w*8..w*8+7, lane -> float4
//   granule of the 128-r stripe, idx from smem (R10-proven inner loop).
// -----------------------------------------------------------------------------
__global__ __launch_bounds__(512)
void fused_kernel(const float* __restrict__ ta, const float* __restrict__ ma,  // A t,m [B,TA]
                  const float* __restrict__ tb, const float* __restrict__ mb_, // B t,m [B,TB]
                  const float* __restrict__ va, const float* __restrict__ vb,  // values [B,C,S]
                  float* __restrict__ aligned,   // [2,B,C,R]
                  float* __restrict__ mask_out,  // [2,B,R]
                  float* __restrict__ idx_out,   // [2,B,R]
                  float* __restrict__ ratio)     // [2,B]
{
    __shared__ float s_t[TB];             // compacted B timestamps (m=1 only)
    __shared__ int   s_i[TB];             // compacted B indices   (m=1 only)
    __shared__ int   s_idx[128];          // per-stripe nearest indices
    __shared__ int   wtot[16], woff[16];
    __shared__ int   s_cnt;

    const int t      = threadIdx.x;
    const int rchunk = blockIdx.x & 15;
    const int mb     = blockIdx.x >> 4;   // 0..31
    const int m      = mb >> 4;
    const int b      = mb & 15;
    const int lane   = t & 31, wid = t >> 5;

    const float* ref_t = ta + (size_t)b * Rn;
    const float* ref_m = ma + (size_t)b * Rn;

    if (t == 0) s_cnt = 0;

    if (m == 0) {
        // ================= m=0 fast path: idx = r (exact) =================
        if (t < 128) {
            const int r = rchunk * 128 + t;
            const float rt = ref_t[r];
            const bool ok = (ref_m[r] > 0.0f);
            int idx = -1;
            if (ok) {
                int e0 = r;
                while (e0 > 0 && ref_t[e0 - 1] == rt) e0--;  // run start (O(1) exp.)
                int s = e0;
                while (ref_m[s] <= 0.0f) s++;                // first valid, s <= r
                idx = s;
            }
            s_idx[t] = idx;
            mask_out[(size_t)mb * Rn + r] = ok ? 1.0f : 0.0f;
            idx_out [(size_t)mb * Rn + r] = ok ? (float)idx : -1.0f;
        }
        if (rchunk == 0) {                // ratio[0,b] = nvA/2048
            int c2 = 0;
            #pragma unroll
            for (int i = 0; i < 4; i++)
                c2 += (ref_m[t * 4 + i] > 0.0f) ? 1 : 0;
            #pragma unroll
            for (int off = 16; off > 0; off >>= 1)
                c2 += __shfl_down_sync(0xffffffffu, c2, off);
            if (lane == 0) atomicAdd(&s_cnt, c2);
        }
        __syncthreads();                  // s_idx (and s_cnt) visible
        if (rchunk == 0 && t == 0)
            ratio[mb] = (float)s_cnt * (1.0f / (float)Rn);
    } else {
        // ============ m=1: compaction (1024, 2/thread) + search ============
        const float* src_t = tb + (size_t)b * TB;
        const float* src_m = mb_ + (size_t)b * TB;

        const float vt0 = src_t[t * 2],     vt1 = src_t[t * 2 + 1];
        const float vm0 = src_m[t * 2],     vm1 = src_m[t * 2 + 1];
        const int   cnt = ((vm0 > 0.0f) ? 1 : 0) + ((vm1 > 0.0f) ? 1 : 0);

        int inc = cnt;                    // warp shuffle scan
        #pragma unroll
        for (int off = 1; off < 32; off <<= 1) {
            int v = __shfl_up_sync(0xffffffffu, inc, off);
            if (lane >= off) inc += v;
        }
        if (lane == 31) wtot[wid] = inc;
        __syncthreads();
        if (t < 16) {
            int v = wtot[t];
            int s = v;
            #pragma unroll
            for (int off = 1; off < 16; off <<= 1) {
                int u = __shfl_up_sync(0x0000ffffu, s, off);
                if (t >= off) s += u;
            }
            woff[t] = s - v;
        }
        __syncthreads();

        int pos = woff[wid] + inc - cnt;
        if (vm0 > 0.0f) { s_t[pos] = vt0; s_i[pos] = t * 2;     pos++; }
        if (vm1 > 0.0f) { s_t[pos] = vt1; s_i[pos] = t * 2 + 1; }
        const int nv = woff[15] + wtot[15];
        __syncthreads();

        if (t < 128) {
            const int r = rchunk * 128 + t;
            const float rt = ref_t[r];
            const bool ok = (ref_m[r] > 0.0f) && (nv > 0);
            int idx = -1;
            if (ok) {
                int lo = 0, hi = nv;      // lower_bound: first s_t[pos] >= rt
                while (lo < hi) {
                    int mid = (lo + hi) >> 1;
                    if (s_t[mid] < rt) lo = mid + 1; else hi = mid;
                }
                int p;
                if (lo == 0) {
                    p = 0;                                      // only right candidate
                } else if (lo == nv || (rt - s_t[lo - 1]) <= (s_t[lo] - rt)) {
                    float tl = s_t[lo - 1];
                    p = lo - 1;
                    while (p > 0 && s_t[p - 1] == tl) p--;      // first duplicate
                } else {
                    p = lo;                                     // lo is first occurrence
                }
                idx = s_i[p];
            }
            s_idx[t] = idx;
            mask_out[(size_t)mb * Rn + r] = ok ? 1.0f : 0.0f;
            idx_out [(size_t)mb * Rn + r] = ok ? (float)idx : -1.0f;
        }
        if (rchunk == 0) {                // count nvA (= valid masks_a[b])
            int c2 = 0;
            #pragma unroll
            for (int i = 0; i < 4; i++)
                c2 += (ref_m[t * 4 + i] > 0.0f) ? 1 : 0;
            #pragma unroll
            for (int off = 16; off > 0; off >>= 1)
                c2 += __shfl_down_sync(0xffffffffu, c2, off);
            if (lane == 0) atomicAdd(&s_cnt, c2);
        }
        __syncthreads();                  // s_idx (and s_cnt) visible
        if (rchunk == 0 && t == 0)
            ratio[mb] = (nv > 0 ? (float)s_cnt : 0.0f) * (1.0f / (float)Rn);
    }

    // ======== gather: warp w -> channels w*8..w*8+7, lane -> float4 ========
    const int    S     = m ? TB : TA;
    const float* vals  = m ? vb : va;
    const int    cb    = wid * 8;         // 16 warps x 8 = 128 channels
    const float* vbase = vals + ((size_t)b * Cn + cb) * S;
    float*       obase = aligned + ((size_t)mb * Cn + cb) * Rn
                                 + rchunk * 128 + lane * 4;

    const int4 ix = *(const int4*)(s_idx + lane * 4);
    const bool vx = ix.x >= 0, vy = ix.y >= 0, vz = ix.z >= 0, vw = ix.w >= 0;

    #pragma unroll
    for (int c = 0; c < 8; c++) {
        const float* vrow = vbase + (size_t)c * S;
        float4 o;
        o.x = vx ? __ldg(vrow + ix.x) : 0.0f;
        o.y = vy ? __ldg(vrow + ix.y) : 0.0f;
        o.z = vz ? __ldg(vrow + ix.z) : 0.0f;
        o.w = vw ? __ldg(vrow + ix.w) : 0.0f;
        *(float4*)(obase + (size_t)c * Rn) = o;
    }
}

extern "C" void kernel_launch(void* const* d_in, const int* in_sizes, int n_in,
                              void* d_out, int out_size)
{
    const float* values_a     = (const float*)d_in[0];
    const float* timestamps_a = (const float*)d_in[1];
    const float* masks_a      = (const float*)d_in[2];
    const float* values_b     = (const float*)d_in[3];
    const float* timestamps_b = (const float*)d_in[4];
    const float* masks_b      = (const float*)d_in[5];
    float* out = (float*)d_out;

    float* aligned = out + OFF_ALIGNED;
    float* maskout = out + OFF_MASK;   // [2,B,R]
    float* idxout  = out + OFF_IDX;    // [2,B,R]
    float* ratio   = out + OFF_RATIO;  // [2,B]

    // Single launch: m-specialized front end + outputs + gather.
    fused_kernel<<<512, 512>>>(timestamps_a, masks_a, timestamps_b, masks_b,
                               values_a, values_b,
                               aligned, maskout, idxout, ratio);

    (void)in_sizes; (void)n_in; (void)out_size;
}